// round 2
// baseline (speedup 1.0000x reference)
#include <cuda_runtime.h>

#define E_TOTAL   32768
#define FEAT_DIM  17
#define HID       64
#define R_DIM     768
#define OUT_PER_EDGE 2304
#define LN_EPS    1e-5f
#define EPB       64            // edges per block (both kernels)
#define NBLK      (E_TOTAL/EPB) // 512

// scratch for h2 (layer-2 output), 32768 x 64 fp32 = 8 MB
__device__ float g_h2[E_TOTAL * HID];

__device__ __forceinline__ float silu_f(float x) {
    return x / (1.0f + __expf(-x));
}

__device__ __forceinline__ void warp_red2(float& s, float& q) {
#pragma unroll
    for (int off = 16; off; off >>= 1) {
        s += __shfl_xor_sync(0xffffffffu, s, off);
        q += __shfl_xor_sync(0xffffffffu, q, off);
    }
}

// ---------------------------------------------------------------------------
// Kernel 1: radial MLP layers 1-2 (Linear->SiLU->LN twice), h2 -> scratch.
// 256 threads = 4 groups of 64; group g handles one edge, thread j = one unit.
// ---------------------------------------------------------------------------
__global__ __launch_bounds__(256) void k1_mlp(
    const float* __restrict__ feat,
    const float* __restrict__ W1, const float* __restrict__ b1, const float* __restrict__ g1,
    const float* __restrict__ W2, const float* __restrict__ b2, const float* __restrict__ g2)
{
    __shared__ float sW1[FEAT_DIM * HID];
    __shared__ float sW2[HID * HID];
    __shared__ float sb1[HID], sg1[HID], sb2[HID], sg2[HID];
    __shared__ float sfeat[4][FEAT_DIM];
    __shared__ float sh[4][HID];
    __shared__ float redS[8], redQ[8];

    const int t = threadIdx.x;
    for (int i = t; i < FEAT_DIM * HID; i += 256) sW1[i] = W1[i];
    for (int i = t; i < HID * HID;     i += 256) sW2[i] = W2[i];
    if (t < HID) { sb1[t] = b1[t]; sg1[t] = g1[t]; sb2[t] = b2[t]; sg2[t] = g2[t]; }

    const int g    = t >> 6;
    const int j    = t & 63;
    const int wid  = t >> 5;
    const int lane = t & 31;
    const int ebase = blockIdx.x * EPB;

    for (int it = 0; it < EPB; it += 4) {
        const int e0 = ebase + it;
        __syncthreads();  // protect sfeat / red arrays across iterations
        if (t < 4 * FEAT_DIM) {
            int e = t / FEAT_DIM, c = t % FEAT_DIM;
            sfeat[e][c] = feat[(size_t)(e0 + e) * FEAT_DIM + c];
        }
        __syncthreads();

        // layer 1
        float x = sb1[j];
#pragma unroll
        for (int c = 0; c < FEAT_DIM; c++) x += sfeat[g][c] * sW1[c * HID + j];
        x = silu_f(x);
        float s = x, q = x * x;
        warp_red2(s, q);
        if (lane == 0) { redS[wid] = s; redQ[wid] = q; }
        __syncthreads();
        s = redS[g * 2] + redS[g * 2 + 1];
        q = redQ[g * 2] + redQ[g * 2 + 1];
        float mu  = s * (1.0f / 64.0f);
        float var = q * (1.0f / 64.0f) - mu * mu;
        float y   = (x - mu) * rsqrtf(var + LN_EPS) * sg1[j];
        sh[g][j] = y;
        __syncthreads();  // sh visible + redS reads done before reuse

        // layer 2
        float x2 = sb2[j];
#pragma unroll
        for (int k = 0; k < HID; k++) x2 += sh[g][k] * sW2[k * HID + j];
        x2 = silu_f(x2);
        s = x2; q = x2 * x2;
        warp_red2(s, q);
        if (lane == 0) { redS[wid] = s; redQ[wid] = q; }
        __syncthreads();
        s = redS[g * 2] + redS[g * 2 + 1];
        q = redQ[g * 2] + redQ[g * 2 + 1];
        mu  = s * (1.0f / 64.0f);
        var = q * (1.0f / 64.0f) - mu * mu;
        float h2 = (x2 - mu) * rsqrtf(var + LN_EPS) * sg2[j];
        g_h2[(size_t)(e0 + g) * HID + j] = h2;
    }
}

// ---------------------------------------------------------------------------
// Kernel 2: r = h2 @ W3 + b3 (W3 in smem), fused with the (o,i,f)x(d,m,f)
// tensor product. Thread t owns triple r[3t..3t+2] = R[o= t/16, i = t%16, :],
// register-blocked over 4 edges, then writes its 9 (d,m) outputs per edge.
// ---------------------------------------------------------------------------
__global__ __launch_bounds__(256) void k2_gemm_tp(
    const float* __restrict__ basis,
    const float* __restrict__ W3, const float* __restrict__ b3,
    float* __restrict__ out)
{
    extern __shared__ float smem[];
    float* sW3  = smem;                    // 64*768 = 49152 floats
    float* sh2  = smem + HID * R_DIM;      // 4*64   = 256 floats
    float* sbas = sh2 + 4 * HID;           // 4*28   = 112 floats (27 used, padded)

    const int t = threadIdx.x;

    // stage W3 (192 KB) once per block, vectorized
    {
        const float4* src = (const float4*)W3;
        float4* dst = (float4*)sW3;
        for (int i = t; i < HID * R_DIM / 4; i += 256) dst[i] = src[i];
    }

    const float br0 = b3[3 * t + 0];
    const float br1 = b3[3 * t + 1];
    const float br2 = b3[3 * t + 2];
    const int o  = t >> 4;
    const int ii = t & 15;
    const int ebase = blockIdx.x * EPB;

    for (int it = 0; it < EPB; it += 4) {
        const int e0 = ebase + it;
        __syncthreads();  // previous-iter consumers done before overwrite (also covers W3 stage)
        {
            int e = t >> 6, kk = t & 63;
            sh2[t] = g_h2[(size_t)(e0 + e) * HID + kk];
        }
        if (t < 4 * 27) {
            int e = t / 27, c = t % 27;
            sbas[e * 28 + c] = basis[(size_t)(e0 + e) * 27 + c];
        }
        __syncthreads();

        float acc[4][3];
#pragma unroll
        for (int e = 0; e < 4; e++) { acc[e][0] = 0.f; acc[e][1] = 0.f; acc[e][2] = 0.f; }

#pragma unroll
        for (int k = 0; k < HID; k += 4) {
            float4 h0 = *(const float4*)&sh2[0 * HID + k];
            float4 h1 = *(const float4*)&sh2[1 * HID + k];
            float4 h2 = *(const float4*)&sh2[2 * HID + k];
            float4 h3 = *(const float4*)&sh2[3 * HID + k];
            float ha[4][4] = {
                {h0.x, h0.y, h0.z, h0.w},
                {h1.x, h1.y, h1.z, h1.w},
                {h2.x, h2.y, h2.z, h2.w},
                {h3.x, h3.y, h3.z, h3.w},
            };
#pragma unroll
            for (int kk = 0; kk < 4; kk++) {
                const float* wr = &sW3[(k + kk) * R_DIM + 3 * t];
                const float w0 = wr[0], w1 = wr[1], w2 = wr[2];
#pragma unroll
                for (int e = 0; e < 4; e++) {
                    acc[e][0] += ha[e][kk] * w0;
                    acc[e][1] += ha[e][kk] * w1;
                    acc[e][2] += ha[e][kk] * w2;
                }
            }
        }

        // tensor product + store: out[(o*3+d)*48 + ii*3 + m]
#pragma unroll
        for (int e = 0; e < 4; e++) {
            const float r0 = acc[e][0] + br0;
            const float r1 = acc[e][1] + br1;
            const float r2 = acc[e][2] + br2;
            const float* B = &sbas[e * 28];
            float* op = out + (size_t)(e0 + e) * OUT_PER_EDGE + o * 144 + ii * 3;
#pragma unroll
            for (int d = 0; d < 3; d++) {
#pragma unroll
                for (int m = 0; m < 3; m++) {
                    const float* bf = B + (d * 3 + m) * 3;
                    op[d * 48 + m] = r0 * bf[0] + r1 * bf[1] + r2 * bf[2];
                }
            }
        }
    }
}

// ---------------------------------------------------------------------------
extern "C" void kernel_launch(void* const* d_in, const int* in_sizes, int n_in,
                              void* d_out, int out_size)
{
    const float* feat  = (const float*)d_in[0];
    const float* basis = (const float*)d_in[1];
    const float* W1    = (const float*)d_in[2];
    const float* b1    = (const float*)d_in[3];
    const float* g1    = (const float*)d_in[4];
    const float* W2    = (const float*)d_in[5];
    const float* b2    = (const float*)d_in[6];
    const float* g2    = (const float*)d_in[7];
    const float* W3    = (const float*)d_in[8];
    const float* b3    = (const float*)d_in[9];
    float* out = (float*)d_out;

    k1_mlp<<<NBLK, 256>>>(feat, W1, b1, g1, W2, b2, g2);

    size_t smem2 = (size_t)(HID * R_DIM + 4 * HID + 4 * 28) * sizeof(float); // 198080 B
    cudaFuncSetAttribute(k2_gemm_tp, cudaFuncAttributeMaxDynamicSharedMemorySize, (int)smem2);
    k2_gemm_tp<<<NBLK, 256, smem2>>>(basis, W3, b3, out);
}

// round 3
// speedup vs baseline: 1.1141x; 1.1141x over previous
#include <cuda_runtime.h>

#define E_TOTAL   32768
#define FEAT_DIM  17
#define HID       64
#define R_DIM     768
#define OUT_PER_EDGE 2304
#define LN_EPS    1e-5f
#define EC        8                    // edges per k2 chunk
#define NCHUNK    (E_TOTAL / EC)       // 4096

// h2 transposed: g_h2T[k][e], 64 x 32768 fp32 = 8 MB
__device__ float g_h2T[HID * E_TOTAL];

// ---------------- packed f32x2 helpers (sm_103a) ----------------
__device__ __forceinline__ unsigned long long pack_ff(float lo, float hi) {
    unsigned long long r;
    asm("mov.b64 %0, {%1, %2};" : "=l"(r) : "f"(lo), "f"(hi));
    return r;
}
__device__ __forceinline__ void ffma2(unsigned long long& d,
                                      unsigned long long a, unsigned long long b) {
    asm("fma.rn.f32x2 %0, %1, %2, %3;" : "=l"(d) : "l"(a), "l"(b), "l"(d));
}
__device__ __forceinline__ void unpack_ff(unsigned long long v, float& lo, float& hi) {
    asm("mov.b64 {%0, %1}, %2;" : "=f"(lo), "=f"(hi) : "l"(v));
}

__device__ __forceinline__ float silu_f(float x) {
    return x / (1.0f + __expf(-x));
}

// ---------------------------------------------------------------------------
// Kernel 1: radial MLP layers 1-2, ONE THREAD PER EDGE.
// LN reductions are in-register (no cross-thread comms). h (layer-1 out) goes
// through smem [k][tid] (conflict-free, same-thread RAW so no syncs needed).
// Output written transposed to g_h2T for k2's vectorized staging.
// ---------------------------------------------------------------------------
__global__ __launch_bounds__(256) void k1_mlp(
    const float* __restrict__ feat,
    const float* __restrict__ W1, const float* __restrict__ b1, const float* __restrict__ g1,
    const float* __restrict__ W2, const float* __restrict__ b2, const float* __restrict__ g2)
{
    __shared__ __align__(16) float sW1[FEAT_DIM * HID];
    __shared__ __align__(16) float sW2[HID * HID];
    __shared__ float sb1[HID], sg1[HID], sb2[HID], sg2[HID];
    extern __shared__ float sh_h[];   // [HID][256] = 64 KB dynamic

    const int t = threadIdx.x;
    for (int i = t; i < FEAT_DIM * HID; i += 256) sW1[i] = W1[i];
    for (int i = t; i < HID * HID;     i += 256) sW2[i] = W2[i];
    if (t < HID) { sb1[t] = b1[t]; sg1[t] = g1[t]; sb2[t] = b2[t]; sg2[t] = g2[t]; }
    __syncthreads();

    const int e = blockIdx.x * 256 + t;
    const float* fr = feat + (size_t)e * FEAT_DIM;

    float x[HID];
#pragma unroll
    for (int j = 0; j < HID; j++) x[j] = sb1[j];

    // layer 1: x = feat @ W1 + b1
#pragma unroll 1
    for (int c = 0; c < FEAT_DIM; c++) {
        const float fv = fr[c];
        const float4* w4 = (const float4*)(sW1 + c * HID);
#pragma unroll
        for (int j4 = 0; j4 < HID / 4; j4++) {
            float4 w = w4[j4];
            x[4*j4+0] = fmaf(fv, w.x, x[4*j4+0]);
            x[4*j4+1] = fmaf(fv, w.y, x[4*j4+1]);
            x[4*j4+2] = fmaf(fv, w.z, x[4*j4+2]);
            x[4*j4+3] = fmaf(fv, w.w, x[4*j4+3]);
        }
    }
    // silu + LN (in-register stats)
    {
        float s = 0.f, q = 0.f;
#pragma unroll
        for (int j = 0; j < HID; j++) {
            x[j] = silu_f(x[j]);
            s += x[j]; q += x[j] * x[j];
        }
        const float mu  = s * (1.0f / 64.0f);
        const float var = q * (1.0f / 64.0f) - mu * mu;
        const float rs  = rsqrtf(var + LN_EPS);
#pragma unroll
        for (int j = 0; j < HID; j++)
            sh_h[j * 256 + t] = (x[j] - mu) * rs * sg1[j];
    }
    // no __syncthreads: each thread reads only its own sh_h column

    // layer 2
#pragma unroll
    for (int j = 0; j < HID; j++) x[j] = sb2[j];
#pragma unroll 1
    for (int k = 0; k < HID; k++) {
        const float hv = sh_h[k * 256 + t];
        const float4* w4 = (const float4*)(sW2 + k * HID);
#pragma unroll
        for (int j4 = 0; j4 < HID / 4; j4++) {
            float4 w = w4[j4];
            x[4*j4+0] = fmaf(hv, w.x, x[4*j4+0]);
            x[4*j4+1] = fmaf(hv, w.y, x[4*j4+1]);
            x[4*j4+2] = fmaf(hv, w.z, x[4*j4+2]);
            x[4*j4+3] = fmaf(hv, w.w, x[4*j4+3]);
        }
    }
    {
        float s = 0.f, q = 0.f;
#pragma unroll
        for (int j = 0; j < HID; j++) {
            x[j] = silu_f(x[j]);
            s += x[j]; q += x[j] * x[j];
        }
        const float mu  = s * (1.0f / 64.0f);
        const float var = q * (1.0f / 64.0f) - mu * mu;
        const float rs  = rsqrtf(var + LN_EPS);
#pragma unroll
        for (int j = 0; j < HID; j++)
            g_h2T[(size_t)j * E_TOTAL + e] = (x[j] - mu) * rs * sg2[j];
    }
}

// ---------------------------------------------------------------------------
// Kernel 2: r = h2 @ W3 + b3 fused with tensor product. 768 threads: thread j
// owns W3 column j IN REGISTERS (64 regs). GEMM uses packed fma.rn.f32x2,
// 2 edges per 64-bit accumulator, h2 via broadcast LDS.128. Persistent blocks
// grid-stride over 8-edge chunks. Epilogue: r triples padded to 16B, basis
// rows padded to 12 floats for vector LDS; coalesced STG.
// ---------------------------------------------------------------------------
__global__ __launch_bounds__(768, 1) void k2_gemm_tp(
    const float* __restrict__ basis,
    const float* __restrict__ W3, const float* __restrict__ b3,
    float* __restrict__ out)
{
    __shared__ __align__(16) float sh2[EC * HID];       // [k][e]  512 f
    __shared__ __align__(16) float sbas[EC * 3 * 12];   // [e][d][12]  288 f
    __shared__ __align__(16) float sr[EC * 256 * 4];    // [e][p][4]  8192 f

    const int t = threadIdx.x;

    // W3 column j -> registers (once per block)
    float wcol[HID];
#pragma unroll
    for (int k = 0; k < HID; k++) wcol[k] = W3[k * R_DIM + t];
    const float bj = b3[t];

    const int jp = t / 3, jc = t - 3 * jp;        // r-staging coords
    const int o  = t / 48;
    const int d  = (t / 16) % 3;
    const int p_t = o * 16 + (t & 15);            // triple index for epilogue

    for (int ch = blockIdx.x; ch < NCHUNK; ch += gridDim.x) {
        const int e0 = ch * EC;

        __syncthreads();   // prev-chunk epilogue done with sbas/sr
        if (t < 128) {
            const int k = t >> 1, half = t & 1;
            const float4 v = *(const float4*)(g_h2T + (size_t)k * E_TOTAL + e0 + 4 * half);
            *(float4*)(sh2 + k * EC + 4 * half) = v;
        }
        if (t < EC * 27) {
            const int e = t / 27, r = t - e * 27;
            const int dd = r / 9, rr = r - dd * 9;
            sbas[(e * 3 + dd) * 12 + rr] = basis[(size_t)(e0 + e) * 27 + r];
        }
        __syncthreads();

        // GEMM: 4 packed accumulators = 8 edges
        unsigned long long acc0 = pack_ff(bj, bj);
        unsigned long long acc1 = acc0, acc2 = acc0, acc3 = acc0;
        const ulonglong2* hb = (const ulonglong2*)sh2;
#pragma unroll
        for (int k = 0; k < HID; k++) {
            const ulonglong2 qa = hb[2 * k];        // edges (0,1),(2,3)
            const ulonglong2 qb = hb[2 * k + 1];    // edges (4,5),(6,7)
            const unsigned long long wp = pack_ff(wcol[k], wcol[k]);
            ffma2(acc0, qa.x, wp);
            ffma2(acc1, qa.y, wp);
            ffma2(acc2, qb.x, wp);
            ffma2(acc3, qb.y, wp);
        }
        {
            float r0, r1;
            unpack_ff(acc0, r0, r1);
            sr[(0 * 256 + jp) * 4 + jc] = r0; sr[(1 * 256 + jp) * 4 + jc] = r1;
            unpack_ff(acc1, r0, r1);
            sr[(2 * 256 + jp) * 4 + jc] = r0; sr[(3 * 256 + jp) * 4 + jc] = r1;
            unpack_ff(acc2, r0, r1);
            sr[(4 * 256 + jp) * 4 + jc] = r0; sr[(5 * 256 + jp) * 4 + jc] = r1;
            unpack_ff(acc3, r0, r1);
            sr[(6 * 256 + jp) * 4 + jc] = r0; sr[(7 * 256 + jp) * 4 + jc] = r1;
        }
        __syncthreads();

        // tensor product + coalesced store: thread t -> out cols [3t, 3t+3)
#pragma unroll
        for (int e = 0; e < EC; e++) {
            const float4 rv = *(const float4*)(sr + (e * 256 + p_t) * 4);
            const float* B = sbas + (e * 3 + d) * 12;
            const float4 b0 = *(const float4*)(B);      // m0f0 m0f1 m0f2 m1f0
            const float4 b1 = *(const float4*)(B + 4);  // m1f1 m1f2 m2f0 m2f1
            const float  b2v = B[8];                    // m2f2
            const float o0 = rv.x * b0.x + rv.y * b0.y + rv.z * b0.z;
            const float o1 = rv.x * b0.w + rv.y * b1.x + rv.z * b1.y;
            const float o2 = rv.x * b1.z + rv.y * b1.w + rv.z * b2v;
            float* op = out + (size_t)(e0 + e) * OUT_PER_EDGE + 3 * t;
            op[0] = o0; op[1] = o1; op[2] = o2;
        }
    }
}

// ---------------------------------------------------------------------------
extern "C" void kernel_launch(void* const* d_in, const int* in_sizes, int n_in,
                              void* d_out, int out_size)
{
    const float* feat  = (const float*)d_in[0];
    const float* basis = (const float*)d_in[1];
    const float* W1    = (const float*)d_in[2];
    const float* b1    = (const float*)d_in[3];
    const float* g1    = (const float*)d_in[4];
    const float* W2    = (const float*)d_in[5];
    const float* b2    = (const float*)d_in[6];
    const float* g2    = (const float*)d_in[7];
    const float* W3    = (const float*)d_in[8];
    const float* b3    = (const float*)d_in[9];
    float* out = (float*)d_out;

    const int k1_dyn = HID * 256 * sizeof(float);  // 64 KB
    cudaFuncSetAttribute(k1_mlp, cudaFuncAttributeMaxDynamicSharedMemorySize, k1_dyn);

    k1_mlp<<<E_TOTAL / 256, 256, k1_dyn>>>(feat, W1, b1, g1, W2, b2, g2);
    k2_gemm_tp<<<148, 768>>>(basis, W3, b3, out);
}

// round 4
// speedup vs baseline: 1.2873x; 1.1555x over previous
#include <cuda_runtime.h>

#define E_TOTAL   32768
#define FEAT_DIM  17
#define HID       64
#define R_DIM     768
#define OUT_PER_EDGE 2304
#define LN_EPS    1e-5f
#define EC        8
#define NCHUNK    (E_TOTAL / EC)       // 4096
#define K2_GRID   148

// h2 transposed: g_h2T[k][e], 64 x 32768 fp32 = 8 MB
__device__ float g_h2T[HID * E_TOTAL];

// ---------------- packed f32x2 helpers (sm_103a) ----------------
__device__ __forceinline__ unsigned long long pack_ff(float lo, float hi) {
    unsigned long long r;
    asm("mov.b64 %0, {%1, %2};" : "=l"(r) : "f"(lo), "f"(hi));
    return r;
}
__device__ __forceinline__ void ffma2(unsigned long long& d,
                                      unsigned long long a, unsigned long long b) {
    asm("fma.rn.f32x2 %0, %1, %2, %3;" : "=l"(d) : "l"(a), "l"(b), "l"(d));
}
__device__ __forceinline__ void unpack_ff(unsigned long long v, float& lo, float& hi) {
    asm("mov.b64 {%0, %1}, %2;" : "=f"(lo), "=f"(hi) : "l"(v));
}

__device__ __forceinline__ float silu_f(float x) {
    return x / (1.0f + __expf(-x));
}

// ---------------------------------------------------------------------------
// Kernel 1: radial MLP layers 1-2, one thread per edge, in-register LN.
// h2 written transposed to g_h2T.
// ---------------------------------------------------------------------------
__global__ __launch_bounds__(256) void k1_mlp(
    const float* __restrict__ feat,
    const float* __restrict__ W1, const float* __restrict__ b1, const float* __restrict__ g1,
    const float* __restrict__ W2, const float* __restrict__ b2, const float* __restrict__ g2)
{
    __shared__ __align__(16) float sW1[FEAT_DIM * HID];
    __shared__ __align__(16) float sW2[HID * HID];
    __shared__ float sb1[HID], sg1[HID], sb2[HID], sg2[HID];
    extern __shared__ float sh_h[];   // [HID][256]

    const int t = threadIdx.x;
    for (int i = t; i < FEAT_DIM * HID; i += 256) sW1[i] = W1[i];
    for (int i = t; i < HID * HID;     i += 256) sW2[i] = W2[i];
    if (t < HID) { sb1[t] = b1[t]; sg1[t] = g1[t]; sb2[t] = b2[t]; sg2[t] = g2[t]; }
    __syncthreads();

    const int e = blockIdx.x * 256 + t;
    const float* fr = feat + (size_t)e * FEAT_DIM;

    float x[HID];
#pragma unroll
    for (int j = 0; j < HID; j++) x[j] = sb1[j];

#pragma unroll 1
    for (int c = 0; c < FEAT_DIM; c++) {
        const float fv = fr[c];
        const float4* w4 = (const float4*)(sW1 + c * HID);
#pragma unroll
        for (int j4 = 0; j4 < HID / 4; j4++) {
            float4 w = w4[j4];
            x[4*j4+0] = fmaf(fv, w.x, x[4*j4+0]);
            x[4*j4+1] = fmaf(fv, w.y, x[4*j4+1]);
            x[4*j4+2] = fmaf(fv, w.z, x[4*j4+2]);
            x[4*j4+3] = fmaf(fv, w.w, x[4*j4+3]);
        }
    }
    {
        float s = 0.f, q = 0.f;
#pragma unroll
        for (int j = 0; j < HID; j++) {
            x[j] = silu_f(x[j]);
            s += x[j]; q += x[j] * x[j];
        }
        const float mu  = s * (1.0f / 64.0f);
        const float var = q * (1.0f / 64.0f) - mu * mu;
        const float rs  = rsqrtf(var + LN_EPS);
#pragma unroll
        for (int j = 0; j < HID; j++)
            sh_h[j * 256 + t] = (x[j] - mu) * rs * sg1[j];
    }

#pragma unroll
    for (int j = 0; j < HID; j++) x[j] = sb2[j];
#pragma unroll 1
    for (int k = 0; k < HID; k++) {
        const float hv = sh_h[k * 256 + t];
        const float4* w4 = (const float4*)(sW2 + k * HID);
#pragma unroll
        for (int j4 = 0; j4 < HID / 4; j4++) {
            float4 w = w4[j4];
            x[4*j4+0] = fmaf(hv, w.x, x[4*j4+0]);
            x[4*j4+1] = fmaf(hv, w.y, x[4*j4+1]);
            x[4*j4+2] = fmaf(hv, w.z, x[4*j4+2]);
            x[4*j4+3] = fmaf(hv, w.w, x[4*j4+3]);
        }
    }
    {
        float s = 0.f, q = 0.f;
#pragma unroll
        for (int j = 0; j < HID; j++) {
            x[j] = silu_f(x[j]);
            s += x[j]; q += x[j] * x[j];
        }
        const float mu  = s * (1.0f / 64.0f);
        const float var = q * (1.0f / 64.0f) - mu * mu;
        const float rs  = rsqrtf(var + LN_EPS);
#pragma unroll
        for (int j = 0; j < HID; j++)
            g_h2T[(size_t)j * E_TOTAL + e] = (x[j] - mu) * rs * sg2[j];
    }
}

// ---------------------------------------------------------------------------
// Kernel 2: pipelined GEMM + tensor product.
//  - W3 column j in registers, FFMA2 packed over 8 edges (4 u64 accumulators)
//  - prefetch next chunk's h2/basis to regs during GEMM, ping-pong smem
//  - epilogue: 576 threads each compute+store one float4 of output (STG.128)
// ---------------------------------------------------------------------------
__global__ __launch_bounds__(768, 1) void k2_gemm_tp(
    const float* __restrict__ basis,
    const float* __restrict__ W3, const float* __restrict__ b3,
    float* __restrict__ out)
{
    __shared__ __align__(16) float sh2[2][EC * HID];   // [buf][k*8+e]
    __shared__ __align__(16) float sbas[2][EC][40];    // [buf][e][d*12 + (m*3+f)]
    __shared__ __align__(16) float sr[EC][256 * 4];    // [e][triple*4 + f]

    const int t = threadIdx.x;

    // W3 column -> registers
    float wcol[HID];
#pragma unroll
    for (int k = 0; k < HID; k++) wcol[k] = W3[k * R_DIM + t];
    const float bj = b3[t];

    const int jp = t / 3, jc = t - 3 * jp;   // GEMM result staging (triple, freq)

    // epilogue mapping: thread c<576 owns output float4 at cols [4c,4c+4)
    const int c    = t;
    const int eo   = c / 36;
    const int ed   = (c / 12) % 3;
    const int pos  = c % 12;
    const int s4   = 4 * pos;
    const int i0   = s4 / 3;
    const int m0   = s4 - 3 * i0;

    int ch = blockIdx.x;
    // prologue stage of first chunk
    {
        const int e0 = ch * EC;
        if (t < 128) {
            const int k = t >> 1, hf = t & 1;
            *(float4*)&sh2[0][k * EC + 4 * hf] =
                *(const float4*)(g_h2T + (size_t)k * E_TOTAL + e0 + 4 * hf);
        }
        if (t < 216) {
            const int e = t / 27, r = t - 27 * e;
            const int dd = r / 9, rr = r - 9 * dd;
            sbas[0][e][dd * 12 + rr] = basis[(size_t)(e0 + e) * 27 + r];
        }
    }
    __syncthreads();

    int buf = 0;
    for (; ch < NCHUNK; ch += K2_GRID, buf ^= 1) {
        const int nxt = ch + K2_GRID;
        const bool hasnext = nxt < NCHUNK;

        // 1. prefetch next chunk to regs (latency hidden by GEMM)
        float4 rh;
        float  rb;
        if (t < 128 && hasnext) {
            const int k = t >> 1, hf = t & 1;
            rh = *(const float4*)(g_h2T + (size_t)k * E_TOTAL + nxt * EC + 4 * hf);
        }
        if (t < 216 && hasnext) {
            rb = basis[(size_t)(nxt * EC + t / 27) * 27 + (t % 27)];
        }

        // 2. GEMM: 4 packed accumulators = 8 edges
        unsigned long long acc0 = pack_ff(bj, bj);
        unsigned long long acc1 = acc0, acc2 = acc0, acc3 = acc0;
        const ulonglong2* hb = (const ulonglong2*)sh2[buf];
#pragma unroll
        for (int k = 0; k < HID; k++) {
            const ulonglong2 qa = hb[2 * k];
            const ulonglong2 qb = hb[2 * k + 1];
            const unsigned long long wp = pack_ff(wcol[k], wcol[k]);
            ffma2(acc0, qa.x, wp);
            ffma2(acc1, qa.y, wp);
            ffma2(acc2, qb.x, wp);
            ffma2(acc3, qb.y, wp);
        }
        // 3. stage r triples
        {
            float r0, r1;
            unpack_ff(acc0, r0, r1);
            sr[0][jp * 4 + jc] = r0; sr[1][jp * 4 + jc] = r1;
            unpack_ff(acc1, r0, r1);
            sr[2][jp * 4 + jc] = r0; sr[3][jp * 4 + jc] = r1;
            unpack_ff(acc2, r0, r1);
            sr[4][jp * 4 + jc] = r0; sr[5][jp * 4 + jc] = r1;
            unpack_ff(acc3, r0, r1);
            sr[6][jp * 4 + jc] = r0; sr[7][jp * 4 + jc] = r1;
        }
        // 4.
        __syncthreads();
        // 5. commit prefetched data to the other buffer
        if (t < 128 && hasnext) {
            const int k = t >> 1, hf = t & 1;
            *(float4*)&sh2[buf ^ 1][k * EC + 4 * hf] = rh;
        }
        if (t < 216 && hasnext) {
            const int e = t / 27, r = t - 27 * e;
            const int dd = r / 9, rr = r - 9 * dd;
            sbas[buf ^ 1][e][dd * 12 + rr] = rb;
        }
        // 6. epilogue: tensor product + STG.128
        if (t < 576) {
            const int e0 = ch * EC;
#pragma unroll
            for (int e = 0; e < EC; e++) {
                const float4 ra = *(const float4*)&sr[e][(eo * 16 + i0) * 4];
                const float4 rbt = *(const float4*)&sr[e][(eo * 16 + i0 + 1) * 4];
                const float* B = &sbas[buf][e][ed * 12];
                const float4 b04 = *(const float4*)(B);
                const float4 b14 = *(const float4*)(B + 4);
                const float  b8  = B[8];
                const float da0 = ra.x * b04.x + ra.y * b04.y + ra.z * b04.z;
                const float da1 = ra.x * b04.w + ra.y * b14.x + ra.z * b14.y;
                const float da2 = ra.x * b14.z + ra.y * b14.w + ra.z * b8;
                const float db0 = rbt.x * b04.x + rbt.y * b04.y + rbt.z * b04.z;
                const float db1 = rbt.x * b04.w + rbt.y * b14.x + rbt.z * b14.y;
                const float db2 = rbt.x * b14.z + rbt.y * b14.w + rbt.z * b8;
                float4 ov;
                ov.x = (m0 == 0) ? da0 : ((m0 == 1) ? da1 : da2);
                ov.y = (m0 == 0) ? da1 : ((m0 == 1) ? da2 : db0);
                ov.z = (m0 == 0) ? da2 : ((m0 == 1) ? db0 : db1);
                ov.w = (m0 == 0) ? db0 : ((m0 == 1) ? db1 : db2);
                *(float4*)(out + (size_t)(e0 + e) * OUT_PER_EDGE + 4 * c) = ov;
            }
        }
        // 7.
        __syncthreads();
    }
}

// ---------------------------------------------------------------------------
extern "C" void kernel_launch(void* const* d_in, const int* in_sizes, int n_in,
                              void* d_out, int out_size)
{
    const float* feat  = (const float*)d_in[0];
    const float* basis = (const float*)d_in[1];
    const float* W1    = (const float*)d_in[2];
    const float* b1    = (const float*)d_in[3];
    const float* g1    = (const float*)d_in[4];
    const float* W2    = (const float*)d_in[5];
    const float* b2    = (const float*)d_in[6];
    const float* g2    = (const float*)d_in[7];
    const float* W3    = (const float*)d_in[8];
    const float* b3    = (const float*)d_in[9];
    float* out = (float*)d_out;

    const int k1_dyn = HID * 256 * sizeof(float);  // 64 KB
    cudaFuncSetAttribute(k1_mlp, cudaFuncAttributeMaxDynamicSharedMemorySize, k1_dyn);

    k1_mlp<<<E_TOTAL / 256, 256, k1_dyn>>>(feat, W1, b1, g1, W2, b2, g2);
    k2_gemm_tp<<<K2_GRID, 768>>>(basis, W3, b3, out);
}

// round 8
// speedup vs baseline: 1.3098x; 1.0175x over previous
#include <cuda_runtime.h>

#define E_TOTAL   32768
#define FEAT_DIM  17
#define HID       64
#define R_DIM     768
#define OUT_PER_EDGE 2304
#define LN_EPS    1e-5f
#define EC        8
#define NCHUNK    (E_TOTAL / EC)       // 4096
#define K2_STRIDE 148
#define K2_GRID   (2 * K2_STRIDE)      // 296: 2 col-halves x 148

// h2 transposed: g_h2T[k][e], 64 x 32768 fp32 = 8 MB
__device__ float g_h2T[HID * E_TOTAL];

// ---------------- packed f32x2 helpers (sm_103a) ----------------
__device__ __forceinline__ unsigned long long pack_ff(float lo, float hi) {
    unsigned long long r;
    asm("mov.b64 %0, {%1, %2};" : "=l"(r) : "f"(lo), "f"(hi));
    return r;
}
__device__ __forceinline__ void ffma2(unsigned long long& d,
                                      unsigned long long a, unsigned long long b) {
    asm("fma.rn.f32x2 %0, %1, %2, %3;" : "=l"(d) : "l"(a), "l"(b), "l"(d));
}
__device__ __forceinline__ void unpack_ff(unsigned long long v, float& lo, float& hi) {
    asm("mov.b64 {%0, %1}, %2;" : "=f"(lo), "=f"(hi) : "l"(v));
}

__device__ __forceinline__ float silu_f(float x) {
    return x / (1.0f + __expf(-x));
}

// ---------------------------------------------------------------------------
// Kernel 1: radial MLP layers 1-2, one thread per edge, in-register LN.
// h2 written transposed to g_h2T.
// ---------------------------------------------------------------------------
__global__ __launch_bounds__(256) void k1_mlp(
    const float* __restrict__ feat,
    const float* __restrict__ W1, const float* __restrict__ b1, const float* __restrict__ g1,
    const float* __restrict__ W2, const float* __restrict__ b2, const float* __restrict__ g2)
{
    __shared__ __align__(16) float sW1[FEAT_DIM * HID];
    __shared__ __align__(16) float sW2[HID * HID];
    __shared__ float sb1[HID], sg1[HID], sb2[HID], sg2[HID];
    extern __shared__ float sh_h[];   // [HID][256]

    const int t = threadIdx.x;
    for (int i = t; i < FEAT_DIM * HID; i += 256) sW1[i] = W1[i];
    for (int i = t; i < HID * HID;     i += 256) sW2[i] = W2[i];
    if (t < HID) { sb1[t] = b1[t]; sg1[t] = g1[t]; sb2[t] = b2[t]; sg2[t] = g2[t]; }
    __syncthreads();

    const int e = blockIdx.x * 256 + t;
    const float* fr = feat + (size_t)e * FEAT_DIM;

    float x[HID];
#pragma unroll
    for (int j = 0; j < HID; j++) x[j] = sb1[j];

#pragma unroll 1
    for (int c = 0; c < FEAT_DIM; c++) {
        const float fv = fr[c];
        const float4* w4 = (const float4*)(sW1 + c * HID);
#pragma unroll
        for (int j4 = 0; j4 < HID / 4; j4++) {
            float4 w = w4[j4];
            x[4*j4+0] = fmaf(fv, w.x, x[4*j4+0]);
            x[4*j4+1] = fmaf(fv, w.y, x[4*j4+1]);
            x[4*j4+2] = fmaf(fv, w.z, x[4*j4+2]);
            x[4*j4+3] = fmaf(fv, w.w, x[4*j4+3]);
        }
    }
    {
        float s = 0.f, q = 0.f;
#pragma unroll
        for (int j = 0; j < HID; j++) {
            x[j] = silu_f(x[j]);
            s += x[j]; q += x[j] * x[j];
        }
        const float mu  = s * (1.0f / 64.0f);
        const float var = q * (1.0f / 64.0f) - mu * mu;
        const float rs  = rsqrtf(var + LN_EPS);
#pragma unroll
        for (int j = 0; j < HID; j++)
            sh_h[j * 256 + t] = (x[j] - mu) * rs * sg1[j];
    }

#pragma unroll
    for (int j = 0; j < HID; j++) x[j] = sb2[j];
#pragma unroll 1
    for (int k = 0; k < HID; k++) {
        const float hv = sh_h[k * 256 + t];
        const float4* w4 = (const float4*)(sW2 + k * HID);
#pragma unroll
        for (int j4 = 0; j4 < HID / 4; j4++) {
            float4 w = w4[j4];
            x[4*j4+0] = fmaf(hv, w.x, x[4*j4+0]);
            x[4*j4+1] = fmaf(hv, w.y, x[4*j4+1]);
            x[4*j4+2] = fmaf(hv, w.z, x[4*j4+2]);
            x[4*j4+3] = fmaf(hv, w.w, x[4*j4+3]);
        }
    }
    {
        float s = 0.f, q = 0.f;
#pragma unroll
        for (int j = 0; j < HID; j++) {
            x[j] = silu_f(x[j]);
            s += x[j]; q += x[j] * x[j];
        }
        const float mu  = s * (1.0f / 64.0f);
        const float var = q * (1.0f / 64.0f) - mu * mu;
        const float rs  = rsqrtf(var + LN_EPS);
#pragma unroll
        for (int j = 0; j < HID; j++)
            g_h2T[(size_t)j * E_TOTAL + e] = (x[j] - mu) * rs * sg2[j];
    }
}

// ---------------------------------------------------------------------------
// Kernel 2: column-split GEMM + tensor product. Each CTA (384 threads) owns
// one 384-col half of W3; 2 CTAs/SM run desynchronized so one CTA's GEMM
// overlaps the other's barrier/epilogue. Per chunk: 8 edges.
//  - W3 column (half*384 + t) in registers, FFMA2 packed over 8 edges
//  - prefetch next chunk's h2/basis to regs during GEMM, ping-pong smem
//  - epilogue: threads t<288 each compute+store one float4 (STG.128)
// ---------------------------------------------------------------------------
__global__ __launch_bounds__(384, 2) void k2_gemm_tp(
    const float* __restrict__ basis,
    const float* __restrict__ W3, const float* __restrict__ b3,
    float* __restrict__ out)
{
    __shared__ __align__(16) float sh2[2][EC * HID];   // [buf][k*8+e]   4 KB
    __shared__ __align__(16) float sbas[2][EC][40];    // [buf][e][d*12+..]
    __shared__ __align__(16) float sr[EC][128 * 4];    // [e][ltriple*4+f] 16 KB

    const int t    = threadIdx.x;
    const int half = blockIdx.x & 1;
    const int jcol = half * 384 + t;

    // W3 column -> registers
    float wcol[HID];
#pragma unroll
    for (int k = 0; k < HID; k++) wcol[k] = W3[k * R_DIM + jcol];
    const float bj = b3[jcol];

    const int jp = t / 3, jc = t - 3 * jp;   // local triple (0..127), freq

    // epilogue mapping: thread t<288 owns output float4 at abs cols 1152*half+4t
    const int eo   = t / 36;                 // local o (0..7)
    const int ed   = (t / 12) % 3;
    const int pos  = t % 12;
    const int s4   = 4 * pos;
    const int i0   = s4 / 3;
    const int m0   = s4 - 3 * i0;

    int ch = blockIdx.x >> 1;
    // prologue stage of first chunk
    {
        const int e0 = ch * EC;
        if (t < 128) {
            const int k = t >> 1, hf = t & 1;
            *(float4*)&sh2[0][k * EC + 4 * hf] =
                *(const float4*)(g_h2T + (size_t)k * E_TOTAL + e0 + 4 * hf);
        }
        if (t < 216) {
            const int e = t / 27, r = t - 27 * e;
            const int dd = r / 9, rr = r - 9 * dd;
            sbas[0][e][dd * 12 + rr] = basis[(size_t)(e0 + e) * 27 + r];
        }
    }
    __syncthreads();

    int buf = 0;
    for (; ch < NCHUNK; ch += K2_STRIDE, buf ^= 1) {
        const int nxt = ch + K2_STRIDE;
        const bool hasnext = nxt < NCHUNK;

        // 1. prefetch next chunk to regs (latency hidden by GEMM)
        float4 rh;
        float  rb;
        if (t < 128 && hasnext) {
            const int k = t >> 1, hf = t & 1;
            rh = *(const float4*)(g_h2T + (size_t)k * E_TOTAL + nxt * EC + 4 * hf);
        }
        if (t < 216 && hasnext) {
            rb = basis[(size_t)(nxt * EC + t / 27) * 27 + (t % 27)];
        }

        // 2. GEMM: 4 packed accumulators = 8 edges
        unsigned long long acc0 = pack_ff(bj, bj);
        unsigned long long acc1 = acc0, acc2 = acc0, acc3 = acc0;
        const ulonglong2* hb = (const ulonglong2*)sh2[buf];
#pragma unroll
        for (int k = 0; k < HID; k++) {
            const ulonglong2 qa = hb[2 * k];
            const ulonglong2 qb = hb[2 * k + 1];
            const unsigned long long wp = pack_ff(wcol[k], wcol[k]);
            ffma2(acc0, qa.x, wp);
            ffma2(acc1, qa.y, wp);
            ffma2(acc2, qb.x, wp);
            ffma2(acc3, qb.y, wp);
        }
        // 3. stage r triples (local)
        {
            float r0, r1;
            unpack_ff(acc0, r0, r1);
            sr[0][jp * 4 + jc] = r0; sr[1][jp * 4 + jc] = r1;
            unpack_ff(acc1, r0, r1);
            sr[2][jp * 4 + jc] = r0; sr[3][jp * 4 + jc] = r1;
            unpack_ff(acc2, r0, r1);
            sr[4][jp * 4 + jc] = r0; sr[5][jp * 4 + jc] = r1;
            unpack_ff(acc3, r0, r1);
            sr[6][jp * 4 + jc] = r0; sr[7][jp * 4 + jc] = r1;
        }
        __syncthreads();
        // 4. commit prefetched data to the other buffer
        if (t < 128 && hasnext) {
            const int k = t >> 1, hf = t & 1;
            *(float4*)&sh2[buf ^ 1][k * EC + 4 * hf] = rh;
        }
        if (t < 216 && hasnext) {
            const int e = t / 27, r = t - 27 * e;
            const int dd = r / 9, rr = r - 9 * dd;
            sbas[buf ^ 1][e][dd * 12 + rr] = rb;
        }
        // 5. epilogue: tensor product + STG.128
        if (t < 288) {
            const int e0 = ch * EC;
            float* ocol = out + 1152 * half + 4 * t;
#pragma unroll
            for (int e = 0; e < EC; e++) {
                const float4 ra  = *(const float4*)&sr[e][(eo * 16 + i0) * 4];
                const float4 rbt = *(const float4*)&sr[e][(eo * 16 + i0 + 1) * 4];
                const float* B = &sbas[buf][e][ed * 12];
                const float4 b04 = *(const float4*)(B);
                const float4 b14 = *(const float4*)(B + 4);
                const float  b8  = B[8];
                const float da0 = ra.x * b04.x + ra.y * b04.y + ra.z * b04.z;
                const float da1 = ra.x * b04.w + ra.y * b14.x + ra.z * b14.y;
                const float da2 = ra.x * b14.z + ra.y * b14.w + ra.z * b8;
                const float db0 = rbt.x * b04.x + rbt.y * b04.y + rbt.z * b04.z;
                const float db1 = rbt.x * b04.w + rbt.y * b14.x + rbt.z * b14.y;
                const float db2 = rbt.x * b14.z + rbt.y * b14.w + rbt.z * b8;
                float4 ov;
                ov.x = (m0 == 0) ? da0 : ((m0 == 1) ? da1 : da2);
                ov.y = (m0 == 0) ? da1 : ((m0 == 1) ? da2 : db0);
                ov.z = (m0 == 0) ? da2 : ((m0 == 1) ? db0 : db1);
                ov.w = (m0 == 0) ? db0 : ((m0 == 1) ? db1 : db2);
                *(float4*)(ocol + (size_t)(e0 + e) * OUT_PER_EDGE) = ov;
            }
        }
        // 6.
        __syncthreads();
    }
}

// ---------------------------------------------------------------------------
extern "C" void kernel_launch(void* const* d_in, const int* in_sizes, int n_in,
                              void* d_out, int out_size)
{
    const float* feat  = (const float*)d_in[0];
    const float* basis = (const float*)d_in[1];
    const float* W1    = (const float*)d_in[2];
    const float* b1    = (const float*)d_in[3];
    const float* g1    = (const float*)d_in[4];
    const float* W2    = (const float*)d_in[5];
    const float* b2    = (const float*)d_in[6];
    const float* g2    = (const float*)d_in[7];
    const float* W3    = (const float*)d_in[8];
    const float* b3    = (const float*)d_in[9];
    float* out = (float*)d_out;

    const int k1_dyn = HID * 256 * sizeof(float);  // 64 KB
    cudaFuncSetAttribute(k1_mlp, cudaFuncAttributeMaxDynamicSharedMemorySize, k1_dyn);

    k1_mlp<<<E_TOTAL / 256, 256, k1_dyn>>>(feat, W1, b1, g1, W2, b2, g2);
    k2_gemm_tp<<<K2_GRID, 384>>>(basis, W3, b3, out);
}